// round 14
// baseline (speedup 1.0000x reference)
#include <cuda_runtime.h>
#include <cuda_fp16.h>
#include <math.h>
#include <stdint.h>

#define HH 65
#define WW 65
#define HW 4225
#define NH 8
#define DK 512
#define RW 33
#define HRW 2145
#define DHID 4096
#define F2W 2113   // words per F2h row ((4225+1)/2)

// ---------------- scratch (device globals) ----------------
__device__ float g_q[DHID];
__device__ float g_up[8 * 4096];
__device__ float g_qb[NH];
__device__ float g_A0p[8 * NH * HW];
__device__ uint32_t g_Wt1p[256 * 1024];        // half2(k,k+1), [kp][br*512+o]
__device__ uint32_t g_Wt2p[2 * 9 * 256 * 512]; // half2, [(bt*256+kpg)][o]
__device__ float g_F1[2 * DK * HW];            // fp32 (for residual)
__device__ uint32_t g_F1h[2 * 256 * HW];       // half2 of relu(F1), k-paired
__device__ uint32_t g_F2h[2 * DK * F2W];       // half2 of relu(F2), s-paired
__device__ float g_F3p[2 * 8 * NH * HW];
__device__ float g_F3[2 * NH * HW];
__device__ float g_filt[2][NH * HRW];
__device__ float2 g_Fr[NH * HRW];
__device__ float2 g_Af[NH * HRW];
__device__ float2 g_Gr[NH * HRW];
__device__ float g_A[NH * HW];
__device__ float g_P[NH * HW];
__device__ float g_m[NH * DK];
__device__ float g_x[DHID];

#define TWO_PI 6.28318530717958647692f

__device__ __forceinline__ uint32_t packh2(float lo, float hi) {
    uint32_t l = __half_as_ushort(__float2half_rn(lo));
    uint32_t h = __half_as_ushort(__float2half_rn(hi));
    return l | (h << 16);
}

__device__ __forceinline__ void mma_f16(
    float& c0, float& c1, float& c2, float& c3,
    uint32_t a0, uint32_t a1, uint32_t a2, uint32_t a3,
    uint32_t b0, uint32_t b1) {
    asm volatile(
        "mma.sync.aligned.m16n8k16.row.col.f32.f16.f16.f32 "
        "{%0,%1,%2,%3},{%4,%5,%6,%7},{%8,%9},{%0,%1,%2,%3};"
        : "+f"(c0), "+f"(c1), "+f"(c2), "+f"(c3)
        : "r"(a0), "r"(a1), "r"(a2), "r"(a3), "r"(b0), "r"(b1));
}

// ---------------- q = Wq @ Q + bq ----------------
__global__ void k_qproj(const float* __restrict__ Q, const float* __restrict__ Wq,
                        const float* __restrict__ bq) {
    int r = blockIdx.x * 8 + (threadIdx.x >> 5);
    int lane = threadIdx.x & 31;
    const float* wr = Wq + r * DK;
    float acc = 0.f;
    for (int c = lane; c < DK; c += 32) acc += wr[c] * Q[c];
    #pragma unroll
    for (int o = 16; o > 0; o >>= 1) acc += __shfl_down_sync(0xffffffffu, acc, o);
    if (lane == 0) g_q[r] = acc + bq[r];
}

// ---------------- qb[h] = q_h . bk_h ----------------
__global__ void k_qb(const float* __restrict__ bk) {
    int h = threadIdx.x >> 5, lane = threadIdx.x & 31;
    float acc = 0.f;
    for (int d = lane; d < DK; d += 32) acc += g_q[h * DK + d] * bk[h * DK + d];
    #pragma unroll
    for (int o = 16; o > 0; o >>= 1) acc += __shfl_down_sync(0xffffffffu, acc, o);
    if (lane == 0) g_qb[h] = acc;
}

// ---------------- u partials ----------------
__global__ void k_u(const float* __restrict__ Wk) {
    int h = blockIdx.x, p = blockIdx.y;
    int tid = threadIdx.x;  // 512
    __shared__ float qs[64];
    if (tid < 64) qs[tid] = g_q[h * DK + p * 64 + tid];
    __syncthreads();
    float acc = 0.f;
    const float* wb = Wk + h * DK * DK + (p * 64) * DK + tid;
    #pragma unroll 8
    for (int d = 0; d < 64; d++) acc += wb[d * DK] * qs[d];
    g_up[p * 4096 + h * DK + tid] = acc;
}

// ---------------- A0 partials over c-chunks of 64 ----------------
__global__ void k_A0p(const float* __restrict__ K) {
    __shared__ float us[NH * 64];
    int tid = threadIdx.x;
    int c0 = blockIdx.y * 64;
    for (int i = tid; i < NH * 64; i += 256) {
        int h = i >> 6, c = i & 63;
        float s = 0.f;
        #pragma unroll
        for (int p = 0; p < 8; p++) s += g_up[p * 4096 + h * DK + c0 + c];
        us[i] = s;
    }
    __syncthreads();
    int s = blockIdx.x * 256 + tid;
    if (s >= HW) return;
    float acc[NH] = {};
    for (int c = 0; c < 64; c++) {
        float kv = K[(c0 + c) * HW + s];
        #pragma unroll
        for (int h = 0; h < NH; h++) acc[h] += us[h * 64 + c] * kv;
    }
    #pragma unroll
    for (int h = 0; h < NH; h++) g_A0p[blockIdx.y * NH * HW + h * HW + s] = acc[h];
}

// ---------------- weight prep: pack half2 along k ----------------
__global__ void k_tr1(const float* __restrict__ amp1, const float* __restrict__ pha1) {
    int idx = blockIdx.x * 256 + threadIdx.x;   // 2*131072
    int br = idx >> 17;
    int r = idx & 131071;
    int kp = r >> 9, o = r & 511;
    const float* src = br ? pha1 : amp1;
    float lo = src[o * DK + 2 * kp];
    float hi = src[o * DK + 2 * kp + 1];
    g_Wt1p[kp * 1024 + br * 512 + o] = packh2(lo, hi);
}

__global__ void k_tr2(const float* __restrict__ amp2, const float* __restrict__ pha2) {
    __shared__ float tile[32][33];
    int bt = blockIdx.x;           // br*9 + t
    int br = bt / 9, t = bt % 9;
    const float* src = br ? pha2 : amp2;
    int o0 = blockIdx.y * 32, i0 = blockIdx.z * 32;
    int tx = threadIdx.x, ty = threadIdx.y;
    #pragma unroll
    for (int r = 0; r < 32; r += 8)
        tile[ty + r][tx] = src[((o0 + ty + r) * DK + i0 + tx) * 9 + t];
    __syncthreads();
    int tid2 = ty * 32 + tx;
    #pragma unroll
    for (int p = 0; p < 2; p++) {
        int wi = tid2 + p * 256;          // 0..511
        int kp_l = wi >> 5, o_l = wi & 31;
        int kpg = (i0 >> 1) + kp_l;
        uint32_t v = packh2(tile[o_l][2 * kp_l], tile[o_l][2 * kp_l + 1]);
        g_Wt2p[((size_t)bt * 256 + kpg) * 512 + o0 + o_l] = v;
    }
}

// ---------------- fp16 tensor-core GEMM / implicit conv ----------------
// Both modes: 32-k stages (16 kp rows), double-buffered, one bar per stage.
// MODE0: A inline from Wt1p; B prefetched from fp32 K (cvt+pack). Writes F1 + F1h.
// MODE1: A inline from Wt2p; B prefetched from F1h. Writes relu(F2) as packed half2.
#define RA 132
#define RB 136

#define DECL_ACC(M,N) float c##M##N##x = 0.f, c##M##N##y = 0.f, c##M##N##z = 0.f, c##M##N##w = 0.f

#define MMA_SLICE(buf, ro) do { \
    uint4 a00 = *(const uint4*)&As[buf][(ro) + tg][aix]; \
    uint4 a01 = *(const uint4*)&As[buf][(ro) + tg][aix + 32]; \
    uint4 a10 = *(const uint4*)&As[buf][(ro) + tg + 4][aix]; \
    uint4 a11 = *(const uint4*)&As[buf][(ro) + tg + 4][aix + 32]; \
    uint4 b0v = *(const uint4*)&Bs[buf][(ro) + tg][bix]; \
    uint4 b1v = *(const uint4*)&Bs[buf][(ro) + tg + 4][bix]; \
    mma_f16(c00x,c00y,c00z,c00w, a00.x,a01.x,a10.x,a11.x, b0v.x,b1v.x); \
    mma_f16(c01x,c01y,c01z,c01w, a00.x,a01.x,a10.x,a11.x, b0v.y,b1v.y); \
    mma_f16(c02x,c02y,c02z,c02w, a00.x,a01.x,a10.x,a11.x, b0v.z,b1v.z); \
    mma_f16(c03x,c03y,c03z,c03w, a00.x,a01.x,a10.x,a11.x, b0v.w,b1v.w); \
    mma_f16(c10x,c10y,c10z,c10w, a00.y,a01.y,a10.y,a11.y, b0v.x,b1v.x); \
    mma_f16(c11x,c11y,c11z,c11w, a00.y,a01.y,a10.y,a11.y, b0v.y,b1v.y); \
    mma_f16(c12x,c12y,c12z,c12w, a00.y,a01.y,a10.y,a11.y, b0v.z,b1v.z); \
    mma_f16(c13x,c13y,c13z,c13w, a00.y,a01.y,a10.y,a11.y, b0v.w,b1v.w); \
    mma_f16(c20x,c20y,c20z,c20w, a00.z,a01.z,a10.z,a11.z, b0v.x,b1v.x); \
    mma_f16(c21x,c21y,c21z,c21w, a00.z,a01.z,a10.z,a11.z, b0v.y,b1v.y); \
    mma_f16(c22x,c22y,c22z,c22w, a00.z,a01.z,a10.z,a11.z, b0v.z,b1v.z); \
    mma_f16(c23x,c23y,c23z,c23w, a00.z,a01.z,a10.z,a11.z, b0v.w,b1v.w); \
    mma_f16(c30x,c30y,c30z,c30w, a00.w,a01.w,a10.w,a11.w, b0v.x,b1v.x); \
    mma_f16(c31x,c31y,c31z,c31w, a00.w,a01.w,a10.w,a11.w, b0v.y,b1v.y); \
    mma_f16(c32x,c32y,c32z,c32w, a00.w,a01.w,a10.w,a11.w, b0v.z,b1v.z); \
    mma_f16(c33x,c33y,c33z,c33w, a00.w,a01.w,a10.w,a11.w, b0v.w,b1v.w); \
} while (0)

// MODE1 B prefetch (from F1h)
#define LDSTAGEB1(s) do { \
    int t_ = (s) >> 4; \
    int kc32_ = (s) & 15; \
    int dy_ = t_ / 3 - 1, dx_ = t_ % 3 - 1; \
    int yy_ = ny + dy_, xx_ = nx + dx_; \
    bool ok_ = nvalid && (unsigned)yy_ < HH && (unsigned)xx_ < WW; \
    int src_ = ok_ ? (yy_ * WW + xx_) : 0; \
    const uint32_t* brow_ = F1hz + (size_t)(kc32_ * 16 + krow0 * 8) * HW + src_; \
    rb0 = ok_ ? brow_[0 * (size_t)HW] : 0u; \
    rb1 = ok_ ? brow_[1 * (size_t)HW] : 0u; \
    rb2 = ok_ ? brow_[2 * (size_t)HW] : 0u; \
    rb3 = ok_ ? brow_[3 * (size_t)HW] : 0u; \
    rb4 = ok_ ? brow_[4 * (size_t)HW] : 0u; \
    rb5 = ok_ ? brow_[5 * (size_t)HW] : 0u; \
    rb6 = ok_ ? brow_[6 * (size_t)HW] : 0u; \
    rb7 = ok_ ? brow_[7 * (size_t)HW] : 0u; \
} while (0)

// MODE0 B prefetch (from fp32 K, cvt+pack)
#define LDSTAGEB0(s) do { \
    int kb_ = ((s) * 16 + krow0 * 8) * 2; \
    if (nvalid) { \
        rb0 = packh2(Kin[(size_t)(kb_ + 0) * HW + n],  Kin[(size_t)(kb_ + 1) * HW + n]); \
        rb1 = packh2(Kin[(size_t)(kb_ + 2) * HW + n],  Kin[(size_t)(kb_ + 3) * HW + n]); \
        rb2 = packh2(Kin[(size_t)(kb_ + 4) * HW + n],  Kin[(size_t)(kb_ + 5) * HW + n]); \
        rb3 = packh2(Kin[(size_t)(kb_ + 6) * HW + n],  Kin[(size_t)(kb_ + 7) * HW + n]); \
        rb4 = packh2(Kin[(size_t)(kb_ + 8) * HW + n],  Kin[(size_t)(kb_ + 9) * HW + n]); \
        rb5 = packh2(Kin[(size_t)(kb_ + 10) * HW + n], Kin[(size_t)(kb_ + 11) * HW + n]); \
        rb6 = packh2(Kin[(size_t)(kb_ + 12) * HW + n], Kin[(size_t)(kb_ + 13) * HW + n]); \
        rb7 = packh2(Kin[(size_t)(kb_ + 14) * HW + n], Kin[(size_t)(kb_ + 15) * HW + n]); \
    } else { rb0=rb1=rb2=rb3=rb4=rb5=rb6=rb7=0u; } \
} while (0)

// store stage: A inline (arow_ set per mode), B from regs
#define STSTAGE_COMMON(buf, arow_, astride_) do { \
    int rbase_ = krow0 * 8; \
    As[buf][rbase_ + 0][physA] = (arow_)[0 * (astride_)]; Bs[buf][rbase_ + 0][physB] = rb0; \
    As[buf][rbase_ + 1][physA] = (arow_)[1 * (astride_)]; Bs[buf][rbase_ + 1][physB] = rb1; \
    As[buf][rbase_ + 2][physA] = (arow_)[2 * (astride_)]; Bs[buf][rbase_ + 2][physB] = rb2; \
    As[buf][rbase_ + 3][physA] = (arow_)[3 * (astride_)]; Bs[buf][rbase_ + 3][physB] = rb3; \
    As[buf][rbase_ + 4][physA] = (arow_)[4 * (astride_)]; Bs[buf][rbase_ + 4][physB] = rb4; \
    As[buf][rbase_ + 5][physA] = (arow_)[5 * (astride_)]; Bs[buf][rbase_ + 5][physB] = rb5; \
    As[buf][rbase_ + 6][physA] = (arow_)[6 * (astride_)]; Bs[buf][rbase_ + 6][physB] = rb6; \
    As[buf][rbase_ + 7][physA] = (arow_)[7 * (astride_)]; Bs[buf][rbase_ + 7][physB] = rb7; \
} while (0)

#define EPI(M,N) do { \
    int mrow = m0 + wm + M*16 + g; \
    int nc = n0 + wn + N*8 + tg*2; \
    if (nc < HW) { \
        if (MODE == 0) { \
            float v0 = c##M##N##x, v1 = c##M##N##y, v2 = c##M##N##z, v3 = c##M##N##w; \
            Yb[(size_t)mrow * HW + nc] = v0; \
            Yb[(size_t)(mrow + 8) * HW + nc] = v2; \
            ((__half*)g_F1h)[((size_t)(mrow >> 1)) * (2 * HW) + 2 * nc + (mrow & 1)] = __float2half_rn(fmaxf(v0, 0.f)); \
            ((__half*)g_F1h)[((size_t)((mrow + 8) >> 1)) * (2 * HW) + 2 * nc + ((mrow + 8) & 1)] = __float2half_rn(fmaxf(v2, 0.f)); \
            if (nc + 1 < HW) { \
                Yb[(size_t)mrow * HW + nc + 1] = v1; \
                Yb[(size_t)(mrow + 8) * HW + nc + 1] = v3; \
                ((__half*)g_F1h)[((size_t)(mrow >> 1)) * (2 * HW) + 2 * (nc + 1) + (mrow & 1)] = __float2half_rn(fmaxf(v1, 0.f)); \
                ((__half*)g_F1h)[((size_t)((mrow + 8) >> 1)) * (2 * HW) + 2 * (nc + 1) + ((mrow + 8) & 1)] = __float2half_rn(fmaxf(v3, 0.f)); \
            } \
        } else { \
            float ra_ = Rb[(size_t)mrow * HW + nc]; \
            float rb_ = (nc + 1 < HW) ? Rb[(size_t)mrow * HW + nc + 1] : 0.f; \
            float rc_ = Rb[(size_t)(mrow + 8) * HW + nc]; \
            float rd_ = (nc + 1 < HW) ? Rb[(size_t)(mrow + 8) * HW + nc + 1] : 0.f; \
            F2hz[(size_t)mrow * F2W + (nc >> 1)] = packh2(fmaxf(c##M##N##x + ra_, 0.f), fmaxf(c##M##N##y + rb_, 0.f)); \
            F2hz[(size_t)(mrow + 8) * F2W + (nc >> 1)] = packh2(fmaxf(c##M##N##z + rc_, 0.f), fmaxf(c##M##N##w + rd_, 0.f)); \
        } \
    } \
} while (0)

template <int MODE>
__global__ void __launch_bounds__(256) k_mma(const float* __restrict__ Kin) {
    __shared__ __align__(16) uint32_t As[2][16][RA];
    __shared__ __align__(16) uint32_t Bs[2][16][RB];
    int tid = threadIdx.x;
    int n0 = blockIdx.x * 128, m0 = blockIdx.y * 128;
    int z = blockIdx.z;

    int col = tid & 127;
    int krow0 = tid >> 7;         // 0 or 1
    int n = n0 + col;
    bool nvalid = n < HW;
    int ny = n / WW, nx = n - ny * WW;

    int physA = ((((col >> 6) * 2 + ((col >> 3) & 1)) * 8 + (col & 7)) * 4) + ((col >> 4) & 3);
    int physB = (col >> 5) * 32 + (col & 7) * 4 + ((col >> 3) & 3);

    int warp = tid >> 5, lane = tid & 31;
    int wm = (warp & 1) * 64, wn = (warp >> 1) * 32;
    int g = lane >> 2, tg = lane & 3;

    int aix = (warp & 1) * 64 + g * 4;
    int bix = (warp >> 1) * 32 + g * 4;

    float* Yb = g_F1;
    const float* Rb = g_F1 + (size_t)z * DK * HW;
    uint32_t* F2hz = g_F2h + (size_t)z * DK * F2W;

    DECL_ACC(0,0); DECL_ACC(0,1); DECL_ACC(0,2); DECL_ACC(0,3);
    DECL_ACC(1,0); DECL_ACC(1,1); DECL_ACC(1,2); DECL_ACC(1,3);
    DECL_ACC(2,0); DECL_ACC(2,1); DECL_ACC(2,2); DECL_ACC(2,3);
    DECL_ACC(3,0); DECL_ACC(3,1); DECL_ACC(3,2); DECL_ACC(3,3);

    uint32_t rb0, rb1, rb2, rb3, rb4, rb5, rb6, rb7;

    if (MODE == 0) {
        const int S = 16;
        LDSTAGEB0(0);
        for (int s = 0; s < S; s++) {
            int buf = s & 1;
            const uint32_t* arow_ = g_Wt1p + (size_t)(s * 16 + krow0 * 8) * 1024 + m0 + col;
            STSTAGE_COMMON(buf, arow_, 1024);
            __syncthreads();
            if (s + 1 < S) LDSTAGEB0(s + 1);
            MMA_SLICE(buf, 0);
            MMA_SLICE(buf, 8);
        }
    } else {
        const int S = 9 * 16;
        const uint32_t* F1hz = g_F1h + (size_t)z * 256 * HW;
        LDSTAGEB1(0);
        for (int s = 0; s < S; s++) {
            int buf = s & 1;
            int t_ = s >> 4, kc32_ = s & 15;
            const uint32_t* arow_ = g_Wt2p + ((size_t)(z * 9 + t_) * 256 + kc32_ * 16 + krow0 * 8) * 512 + m0 + col;
            STSTAGE_COMMON(buf, arow_, 512);
            __syncthreads();
            if (s + 1 < S) LDSTAGEB1(s + 1);
            MMA_SLICE(buf, 0);
            MMA_SLICE(buf, 8);
        }
    }

    EPI(0,0); EPI(0,1); EPI(0,2); EPI(0,3);
    EPI(1,0); EPI(1,1); EPI(1,2); EPI(1,3);
    EPI(2,0); EPI(2,1); EPI(2,2); EPI(2,3);
    EPI(3,0); EPI(3,1); EPI(3,2); EPI(3,3);
}

// ---------------- F3 partials: half2 F2, 2 s-positions per thread ----------------
__global__ void k_f3p(const float* __restrict__ amp3, const float* __restrict__ pha3) {
    __shared__ float ws[NH * 64];
    int tid = threadIdx.x;
    int c0 = blockIdx.y * 64;
    int br = blockIdx.z;
    const float* W3 = br ? pha3 : amp3;
    const uint32_t* F2b = g_F2h + (size_t)br * DK * F2W;
    for (int i = tid; i < NH * 64; i += 256) {
        int h = i >> 6, c = i & 63;
        ws[i] = W3[h * DK + c0 + c];
    }
    __syncthreads();
    int sp = blockIdx.x * 256 + tid;
    if (sp >= F2W) return;
    int s0 = 2 * sp;
    float acc0[NH] = {}, acc1[NH] = {};
    for (int c = 0; c < 64; c++) {
        uint32_t u = F2b[(size_t)(c0 + c) * F2W + sp];
        __half2 hv = *reinterpret_cast<const __half2*>(&u);
        float2 f = __half22float2(hv);
        #pragma unroll
        for (int h = 0; h < NH; h++) {
            acc0[h] += ws[h * 64 + c] * f.x;
            acc1[h] += ws[h * 64 + c] * f.y;
        }
    }
    float* outp = g_F3p + ((size_t)br * 8 + blockIdx.y) * NH * HW;
    #pragma unroll
    for (int h = 0; h < NH; h++) {
        outp[h * HW + s0] = acc0[h];
        if (s0 + 1 < HW) outp[h * HW + s0 + 1] = acc1[h];
    }
}

__global__ void k_f3red() {
    int idx = blockIdx.x * 256 + threadIdx.x;
    if (idx >= NH * HW) return;
    int br = blockIdx.y;
    const float* p = g_F3p + (size_t)br * 8 * NH * HW;
    float s = 0.f;
    #pragma unroll
    for (int i = 0; i < 8; i++) s += p[i * NH * HW + idx];
    g_F3[br * NH * HW + idx] = fmaxf(s, 0.f);
}

// ---------------- down-proj (warp per output j) ----------------
__global__ void k_down(const float* __restrict__ Wd1, const float* __restrict__ bd1,
                       const float* __restrict__ Wd2, const float* __restrict__ bd2) {
    int warp = threadIdx.x >> 5, lane = threadIdx.x & 31;
    int j = blockIdx.x * 8 + warp;
    int br = blockIdx.y;
    if (j >= HRW) return;
    const float* Wd = br ? Wd2 : Wd1;
    const float* bd = br ? bd2 : bd1;
    const float* F3b = g_F3 + br * NH * HW;
    const float* wr = Wd + (size_t)j * HW;
    float acc[NH] = {};
    for (int s = lane; s < HW; s += 32) {
        float wv = wr[s];
        #pragma unroll
        for (int h = 0; h < NH; h++) acc[h] += wv * F3b[h * HW + s];
    }
    #pragma unroll
    for (int h = 0; h < NH; h++) {
        #pragma unroll
        for (int o = 16; o > 0; o >>= 1) acc[h] += __shfl_down_sync(0xffffffffu, acc[h], o);
    }
    if (lane == 0) {
        float b = bd[j];
        #pragma unroll
        for (int h = 0; h < NH; h++) g_filt[br][h * HRW + j] = acc[h] + b;
    }
}

// ---------------- FFT chain (A0 reduction fused into row FFT) ----------------
__global__ void k_fftrow() {
    int hy = blockIdx.x;
    int h = hy / HH, y = hy % HH;
    __shared__ float row[HH], twc[HH], tws[HH];
    int tid = threadIdx.x;  // 64
    for (int i = tid; i < HH; i += 64) {
        float s = 0.f;
        #pragma unroll
        for (int p = 0; p < 8; p++) s += g_A0p[p * NH * HW + h * HW + y * WW + i];
        row[i] = (s + g_qb[h]) * 0.04419417382415922f;
        float sv, cv;
        sincosf(TWO_PI * (float)i / 65.f, &sv, &cv);
        twc[i] = cv; tws[i] = sv;
    }
    __syncthreads();
    if (tid < RW) {
        float re = 0.f, im = 0.f;
        for (int x = 0; x < HH; x++) {
            int t = (tid * x) % 65;
            re += row[x] * twc[t];
            im -= row[x] * tws[t];
        }
        g_Fr[h * HRW + y * RW + tid] = make_float2(re, im);
    }
}

__global__ void k_fftcol_mod() {
    __shared__ float twc[HH], tws[HH];
    for (int i = threadIdx.x; i < HH; i += 256) {
        float sv, cv;
        sincosf(TWO_PI * (float)i / 65.f, &sv, &cv);
        twc[i] = cv; tws[i] = sv;
    }
    __syncthreads();
    int idx = blockIdx.x * 256 + threadIdx.x;
    if (idx >= NH * HRW) return;
    int h = idx / HRW, r = idx % HRW;
    int ky = r / RW, kx = r % RW;
    const float2* fr = g_Fr + h * HRW + kx;
    float re = 0.f, im = 0.f;
    for (int y = 0; y < HH; y++) {
        int t = (ky * y) % 65;
        float c = twc[t], s = tws[t];
        float2 f = fr[y * RW];
        re += f.x * c + f.y * s;
        im += f.y * c - f.x * s;
    }
    float mag = sqrtf(re * re + im * im);
    float ang = atan2f(im, re);
    float a = g_filt[0][idx] * mag;
    float p = g_filt[1][idx] * ang;
    float sp, cp;
    sincosf(p, &sp, &cp);
    g_Af[idx] = make_float2(a * cp, a * sp);
}

__global__ void k_invcol() {
    __shared__ float twc[HH], tws[HH];
    for (int i = threadIdx.x; i < HH; i += 256) {
        float sv, cv;
        sincosf(TWO_PI * (float)i / 65.f, &sv, &cv);
        twc[i] = cv; tws[i] = sv;
    }
    __syncthreads();
    int idx = blockIdx.x * 256 + threadIdx.x;
    if (idx >= NH * HRW) return;
    int h = idx / HRW, r = idx % HRW;
    int y = r / RW, kx = r % RW;
    const float2* af = g_Af + h * HRW + kx;
    float re = 0.f, im = 0.f;
    for (int ky = 0; ky < HH; ky++) {
        int t = (ky * y) % 65;
        float c = twc[t], s = tws[t];
        float2 f = af[ky * RW];
        re += f.x * c - f.y * s;
        im += f.y * c + f.x * s;
    }
    g_Gr[idx] = make_float2(re * (1.f / 65.f), im * (1.f / 65.f));
}

__global__ void k_invrow() {
    __shared__ float twc[HH], tws[HH];
    for (int i = threadIdx.x; i < HH; i += 256) {
        float sv, cv;
        sincosf(TWO_PI * (float)i / 65.f, &sv, &cv);
        twc[i] = cv; tws[i] = sv;
    }
    __syncthreads();
    int idx = blockIdx.x * 256 + threadIdx.x;
    if (idx >= NH * HW) return;
    int h = idx / HW, s = idx % HW;
    int y = s / WW, x = s % WW;
    const float2* gp = g_Gr + h * HRW + y * RW;
    float acc = gp[0].x;
    for (int k = 1; k < RW; k++) {
        int t = (k * x) % 65;
        acc += 2.f * (gp[k].x * twc[t] - gp[k].y * tws[t]);
    }
    g_A[idx] = acc * (1.f / 65.f);
}

// ---------------- softmax per head (1024 threads) ----------------
__global__ void k_softmax() {
    int h = blockIdx.x, tid = threadIdx.x;
    __shared__ float red[1024];
    const float* a = g_A + h * HW;
    float* p = g_P + h * HW;
    float mx = -3.4e38f;
    for (int s = tid; s < HW; s += 1024) mx = fmaxf(mx, a[s]);
    red[tid] = mx;
    __syncthreads();
    for (int st = 512; st > 0; st >>= 1) {
        if (tid < st) red[tid] = fmaxf(red[tid], red[tid + st]);
        __syncthreads();
    }
    mx = red[0];
    __syncthreads();
    float sum = 0.f;
    for (int s = tid; s < HW; s += 1024) {
        float e = expf(a[s] - mx);
        p[s] = e;
        sum += e;
    }
    red[tid] = sum;
    __syncthreads();
    for (int st = 512; st > 0; st >>= 1) {
        if (tid < st) red[tid] += red[tid + st];
        __syncthreads();
    }
    float inv = 1.f / red[0];
    for (int s = tid; s < HW; s += 1024) p[s] *= inv;
}

// ---------------- m[h,c] = sum_s P[h,s]*K[c,s] ----------------
__global__ void k_m(const float* __restrict__ K) {
    int c = blockIdx.x * 8 + (threadIdx.x >> 5);
    int lane = threadIdx.x & 31;
    const float* kr = K + c * HW;
    float acc[NH] = {};
    for (int s = lane; s < HW; s += 32) {
        float kv = kr[s];
        #pragma unroll
        for (int h = 0; h < NH; h++) acc[h] += kv * g_P[h * HW + s];
    }
    #pragma unroll
    for (int h = 0; h < NH; h++) {
        #pragma unroll
        for (int o = 16; o > 0; o >>= 1) acc[h] += __shfl_down_sync(0xffffffffu, acc[h], o);
    }
    if (lane == 0) {
        #pragma unroll
        for (int h = 0; h < NH; h++) g_m[h * DK + c] = acc[h];
    }
}

__global__ void k_vproj(const float* __restrict__ Wv, const float* __restrict__ bv) {
    int r = blockIdx.x * 8 + (threadIdx.x >> 5);
    int lane = threadIdx.x & 31;
    int h = r >> 9;
    const float* mr = g_m + (h << 9);
    const float* wr = Wv + r * DK;
    float acc = 0.f;
    for (int c = lane; c < DK; c += 32) acc += wr[c] * mr[c];
    #pragma unroll
    for (int o = 16; o > 0; o >>= 1) acc += __shfl_down_sync(0xffffffffu, acc, o);
    if (lane == 0) g_x[r] = acc + bv[r];
}

__global__ void k_out(const float* __restrict__ Wo, const float* __restrict__ bo,
                      float* __restrict__ out) {
    int r = blockIdx.x * 8 + (threadIdx.x >> 5);
    int lane = threadIdx.x & 31;
    const float* wr = Wo + r * DHID;
    float acc = 0.f;
    for (int j = lane; j < DHID; j += 32) acc += wr[j] * g_x[j];
    #pragma unroll
    for (int o = 16; o > 0; o >>= 1) acc += __shfl_down_sync(0xffffffffu, acc, o);
    if (lane == 0) out[r] = acc + bo[r];
}

extern "C" void kernel_launch(void* const* d_in, const int* in_sizes, int n_in,
                              void* d_out, int out_size) {
    const float* Q    = (const float*)d_in[0];
    const float* K    = (const float*)d_in[1];
    const float* Wq   = (const float*)d_in[2];
    const float* bq   = (const float*)d_in[3];
    const float* Wk   = (const float*)d_in[4];
    const float* bk   = (const float*)d_in[5];
    const float* Wv   = (const float*)d_in[6];
    const float* bv   = (const float*)d_in[7];
    const float* Wo   = (const float*)d_in[8];
    const float* bo   = (const float*)d_in[9];
    const float* amp1 = (const float*)d_in[10];
    const float* amp2 = (const float*)d_in[11];
    const float* amp3 = (const float*)d_in[12];
    const float* pha1 = (const float*)d_in[13];
    const float* pha2 = (const float*)d_in[14];
    const float* pha3 = (const float*)d_in[15];
    const float* Wd1  = (const float*)d_in[16];
    const float* bd1  = (const float*)d_in[17];
    const float* Wd2  = (const float*)d_in[18];
    const float* bd2  = (const float*)d_in[19];
    float* out = (float*)d_out;

    // conv path first: positions k_mma<1> at launch #4 (where ncu samples)
    k_tr1<<<1024, 256>>>(amp1, pha1);                                    // 1
    k_tr2<<<dim3(18, 16, 16), dim3(32, 8)>>>(amp2, pha2);                // 2
    k_mma<0><<<dim3(34, 8, 1), 256>>>(K);                                // 3
    k_mma<1><<<dim3(34, 4, 2), 256>>>(K);                                // 4

    // attention-score path
    k_qproj<<<512, 256>>>(Q, Wq, bq);
    k_qb<<<1, 256>>>(bk);
    k_u<<<dim3(8, 8), 512>>>(Wk);
    k_A0p<<<dim3(17, 8), 256>>>(K);

    k_f3p<<<dim3(9, 8, 2), 256>>>(amp3, pha3);
    k_f3red<<<dim3(133, 2), 256>>>();
    k_down<<<dim3(269, 2), 256>>>(Wd1, bd1, Wd2, bd2);

    // spectral filtering (A0 reduce fused into fftrow)
    k_fftrow<<<NH * HH, 64>>>();
    k_fftcol_mod<<<68, 256>>>();
    k_invcol<<<68, 256>>>();
    k_invrow<<<133, 256>>>();
    k_softmax<<<NH, 1024>>>();

    // output path
    k_m<<<64, 256>>>(K);
    k_vproj<<<512, 256>>>(Wv, bv);
    k_out<<<64, 256>>>(Wo, bo, out);
}

// round 16
// speedup vs baseline: 1.0086x; 1.0086x over previous
#include <cuda_runtime.h>
#include <cuda_fp16.h>
#include <math.h>
#include <stdint.h>

#define HH 65
#define WW 65
#define HW 4225
#define NH 8
#define DK 512
#define RW 33
#define HRW 2145
#define DHID 4096
#define F2W 2113   // words per F2h row ((4225+1)/2)

// ---------------- scratch (device globals) ----------------
__device__ float g_q[DHID];
__device__ float g_up[8 * 4096];
__device__ float g_qb[NH];
__device__ float g_A0p[8 * NH * HW];
__device__ uint32_t g_Wt1p[256 * 1024];        // half2(k,k+1), [kp][br*512+o]
__device__ uint32_t g_Wt2p[2 * 9 * 256 * 512]; // half2, [(bt*256+kpg)][o]
__device__ float g_F1[2 * DK * HW];            // fp32 (for residual)
__device__ uint32_t g_F1h[2 * 256 * HW];       // half2 of relu(F1), k-paired
__device__ uint32_t g_F2h[2 * DK * F2W];       // half2 of relu(F2), s-paired
__device__ float g_F3p[2 * 16 * NH * HW];
__device__ float g_F3[2 * NH * HW];
__device__ float g_filt[2][NH * HRW];
__device__ float2 g_Fr[NH * HRW];
__device__ float2 g_Af[NH * HRW];
__device__ float2 g_Gr[NH * HRW];
__device__ float g_A[NH * HW];
__device__ float g_P[NH * HW];
__device__ float g_m[NH * DK];
__device__ float g_x[DHID];

#define TWO_PI 6.28318530717958647692f

__device__ __forceinline__ uint32_t packh2(float lo, float hi) {
    uint32_t l = __half_as_ushort(__float2half_rn(lo));
    uint32_t h = __half_as_ushort(__float2half_rn(hi));
    return l | (h << 16);
}

__device__ __forceinline__ void mma_f16(
    float& c0, float& c1, float& c2, float& c3,
    uint32_t a0, uint32_t a1, uint32_t a2, uint32_t a3,
    uint32_t b0, uint32_t b1) {
    asm volatile(
        "mma.sync.aligned.m16n8k16.row.col.f32.f16.f16.f32 "
        "{%0,%1,%2,%3},{%4,%5,%6,%7},{%8,%9},{%0,%1,%2,%3};"
        : "+f"(c0), "+f"(c1), "+f"(c2), "+f"(c3)
        : "r"(a0), "r"(a1), "r"(a2), "r"(a3), "r"(b0), "r"(b1));
}

// ---------------- q = Wq @ Q + bq ----------------
__global__ void k_qproj(const float* __restrict__ Q, const float* __restrict__ Wq,
                        const float* __restrict__ bq) {
    int r = blockIdx.x * 8 + (threadIdx.x >> 5);
    int lane = threadIdx.x & 31;
    const float* wr = Wq + r * DK;
    float acc = 0.f;
    for (int c = lane; c < DK; c += 32) acc += wr[c] * Q[c];
    #pragma unroll
    for (int o = 16; o > 0; o >>= 1) acc += __shfl_down_sync(0xffffffffu, acc, o);
    if (lane == 0) g_q[r] = acc + bq[r];
}

// ---------------- qb[h] = q_h . bk_h ----------------
__global__ void k_qb(const float* __restrict__ bk) {
    int h = threadIdx.x >> 5, lane = threadIdx.x & 31;
    float acc = 0.f;
    for (int d = lane; d < DK; d += 32) acc += g_q[h * DK + d] * bk[h * DK + d];
    #pragma unroll
    for (int o = 16; o > 0; o >>= 1) acc += __shfl_down_sync(0xffffffffu, acc, o);
    if (lane == 0) g_qb[h] = acc;
}

// ---------------- u partials ----------------
__global__ void k_u(const float* __restrict__ Wk) {
    int h = blockIdx.x, p = blockIdx.y;
    int tid = threadIdx.x;  // 512
    __shared__ float qs[64];
    if (tid < 64) qs[tid] = g_q[h * DK + p * 64 + tid];
    __syncthreads();
    float acc = 0.f;
    const float* wb = Wk + h * DK * DK + (p * 64) * DK + tid;
    #pragma unroll 8
    for (int d = 0; d < 64; d++) acc += wb[d * DK] * qs[d];
    g_up[p * 4096 + h * DK + tid] = acc;
}

// ---------------- A0 partials over c-chunks of 64 ----------------
__global__ void k_A0p(const float* __restrict__ K) {
    __shared__ float us[NH * 64];
    int tid = threadIdx.x;
    int c0 = blockIdx.y * 64;
    for (int i = tid; i < NH * 64; i += 256) {
        int h = i >> 6, c = i & 63;
        float s = 0.f;
        #pragma unroll
        for (int p = 0; p < 8; p++) s += g_up[p * 4096 + h * DK + c0 + c];
        us[i] = s;
    }
    __syncthreads();
    int s = blockIdx.x * 256 + tid;
    if (s >= HW) return;
    float acc[NH] = {};
    for (int c = 0; c < 64; c++) {
        float kv = K[(c0 + c) * HW + s];
        #pragma unroll
        for (int h = 0; h < NH; h++) acc[h] += us[h * 64 + c] * kv;
    }
    #pragma unroll
    for (int h = 0; h < NH; h++) g_A0p[blockIdx.y * NH * HW + h * HW + s] = acc[h];
}

// ---------------- weight prep: pack half2 along k ----------------
__global__ void k_tr1(const float* __restrict__ amp1, const float* __restrict__ pha1) {
    int idx = blockIdx.x * 256 + threadIdx.x;   // 2*131072
    int br = idx >> 17;
    int r = idx & 131071;
    int kp = r >> 9, o = r & 511;
    const float* src = br ? pha1 : amp1;
    float lo = src[o * DK + 2 * kp];
    float hi = src[o * DK + 2 * kp + 1];
    g_Wt1p[kp * 1024 + br * 512 + o] = packh2(lo, hi);
}

__global__ void k_tr2(const float* __restrict__ amp2, const float* __restrict__ pha2) {
    __shared__ float tile[32][33];
    int bt = blockIdx.x;           // br*9 + t
    int br = bt / 9, t = bt % 9;
    const float* src = br ? pha2 : amp2;
    int o0 = blockIdx.y * 32, i0 = blockIdx.z * 32;
    int tx = threadIdx.x, ty = threadIdx.y;
    #pragma unroll
    for (int r = 0; r < 32; r += 8)
        tile[ty + r][tx] = src[((o0 + ty + r) * DK + i0 + tx) * 9 + t];
    __syncthreads();
    int tid2 = ty * 32 + tx;
    #pragma unroll
    for (int p = 0; p < 2; p++) {
        int wi = tid2 + p * 256;          // 0..511
        int kp_l = wi >> 5, o_l = wi & 31;
        int kpg = (i0 >> 1) + kp_l;
        uint32_t v = packh2(tile[o_l][2 * kp_l], tile[o_l][2 * kp_l + 1]);
        g_Wt2p[((size_t)bt * 256 + kpg) * 512 + o0 + o_l] = v;
    }
}

// ---------------- fp16 tensor-core GEMM / implicit conv ----------------
#define RA 132
#define RB 136

#define DECL_ACC(M,N) float c##M##N##x = 0.f, c##M##N##y = 0.f, c##M##N##z = 0.f, c##M##N##w = 0.f

#define MMA_SLICE(buf, ro) do { \
    uint4 a00 = *(const uint4*)&As[buf][(ro) + tg][aix]; \
    uint4 a01 = *(const uint4*)&As[buf][(ro) + tg][aix + 32]; \
    uint4 a10 = *(const uint4*)&As[buf][(ro) + tg + 4][aix]; \
    uint4 a11 = *(const uint4*)&As[buf][(ro) + tg + 4][aix + 32]; \
    uint4 b0v = *(const uint4*)&Bs[buf][(ro) + tg][bix]; \
    uint4 b1v = *(const uint4*)&Bs[buf][(ro) + tg + 4][bix]; \
    mma_f16(c00x,c00y,c00z,c00w, a00.x,a01.x,a10.x,a11.x, b0v.x,b1v.x); \
    mma_f16(c01x,c01y,c01z,c01w, a00.x,a01.x,a10.x,a11.x, b0v.y,b1v.y); \
    mma_f16(c02x,c02y,c02z,c02w, a00.x,a01.x,a10.x,a11.x, b0v.z,b1v.z); \
    mma_f16(c03x,c03y,c03z,c03w, a00.x,a01.x,a10.x,a11.x, b0v.w,b1v.w); \
    mma_f16(c10x,c10y,c10z,c10w, a00.y,a01.y,a10.y,a11.y, b0v.x,b1v.x); \
    mma_f16(c11x,c11y,c11z,c11w, a00.y,a01.y,a10.y,a11.y, b0v.y,b1v.y); \
    mma_f16(c12x,c12y,c12z,c12w, a00.y,a01.y,a10.y,a11.y, b0v.z,b1v.z); \
    mma_f16(c13x,c13y,c13z,c13w, a00.y,a01.y,a10.y,a11.y, b0v.w,b1v.w); \
    mma_f16(c20x,c20y,c20z,c20w, a00.z,a01.z,a10.z,a11.z, b0v.x,b1v.x); \
    mma_f16(c21x,c21y,c21z,c21w, a00.z,a01.z,a10.z,a11.z, b0v.y,b1v.y); \
    mma_f16(c22x,c22y,c22z,c22w, a00.z,a01.z,a10.z,a11.z, b0v.z,b1v.z); \
    mma_f16(c23x,c23y,c23z,c23w, a00.z,a01.z,a10.z,a11.z, b0v.w,b1v.w); \
    mma_f16(c30x,c30y,c30z,c30w, a00.w,a01.w,a10.w,a11.w, b0v.x,b1v.x); \
    mma_f16(c31x,c31y,c31z,c31w, a00.w,a01.w,a10.w,a11.w, b0v.y,b1v.y); \
    mma_f16(c32x,c32y,c32z,c32w, a00.w,a01.w,a10.w,a11.w, b0v.z,b1v.z); \
    mma_f16(c33x,c33y,c33z,c33w, a00.w,a01.w,a10.w,a11.w, b0v.w,b1v.w); \
} while (0)

#define LDSTAGEB1(s) do { \
    int t_ = (s) >> 4; \
    int kc32_ = (s) & 15; \
    int dy_ = t_ / 3 - 1, dx_ = t_ % 3 - 1; \
    int yy_ = ny + dy_, xx_ = nx + dx_; \
    bool ok_ = nvalid && (unsigned)yy_ < HH && (unsigned)xx_ < WW; \
    int src_ = ok_ ? (yy_ * WW + xx_) : 0; \
    const uint32_t* brow_ = F1hz + (size_t)(kc32_ * 16 + krow0 * 8) * HW + src_; \
    rb0 = ok_ ? brow_[0 * (size_t)HW] : 0u; \
    rb1 = ok_ ? brow_[1 * (size_t)HW] : 0u; \
    rb2 = ok_ ? brow_[2 * (size_t)HW] : 0u; \
    rb3 = ok_ ? brow_[3 * (size_t)HW] : 0u; \
    rb4 = ok_ ? brow_[4 * (size_t)HW] : 0u; \
    rb5 = ok_ ? brow_[5 * (size_t)HW] : 0u; \
    rb6 = ok_ ? brow_[6 * (size_t)HW] : 0u; \
    rb7 = ok_ ? brow_[7 * (size_t)HW] : 0u; \
} while (0)

#define LDSTAGEB0(s) do { \
    int kb_ = ((s) * 16 + krow0 * 8) * 2; \
    if (nvalid) { \
        rb0 = packh2(Kin[(size_t)(kb_ + 0) * HW + n],  Kin[(size_t)(kb_ + 1) * HW + n]); \
        rb1 = packh2(Kin[(size_t)(kb_ + 2) * HW + n],  Kin[(size_t)(kb_ + 3) * HW + n]); \
        rb2 = packh2(Kin[(size_t)(kb_ + 4) * HW + n],  Kin[(size_t)(kb_ + 5) * HW + n]); \
        rb3 = packh2(Kin[(size_t)(kb_ + 6) * HW + n],  Kin[(size_t)(kb_ + 7) * HW + n]); \
        rb4 = packh2(Kin[(size_t)(kb_ + 8) * HW + n],  Kin[(size_t)(kb_ + 9) * HW + n]); \
        rb5 = packh2(Kin[(size_t)(kb_ + 10) * HW + n], Kin[(size_t)(kb_ + 11) * HW + n]); \
        rb6 = packh2(Kin[(size_t)(kb_ + 12) * HW + n], Kin[(size_t)(kb_ + 13) * HW + n]); \
        rb7 = packh2(Kin[(size_t)(kb_ + 14) * HW + n], Kin[(size_t)(kb_ + 15) * HW + n]); \
    } else { rb0=rb1=rb2=rb3=rb4=rb5=rb6=rb7=0u; } \
} while (0)

#define STSTAGE_COMMON(buf, arow_, astride_) do { \
    int rbase_ = krow0 * 8; \
    As[buf][rbase_ + 0][physA] = (arow_)[0 * (astride_)]; Bs[buf][rbase_ + 0][physB] = rb0; \
    As[buf][rbase_ + 1][physA] = (arow_)[1 * (astride_)]; Bs[buf][rbase_ + 1][physB] = rb1; \
    As[buf][rbase_ + 2][physA] = (arow_)[2 * (astride_)]; Bs[buf][rbase_ + 2][physB] = rb2; \
    As[buf][rbase_ + 3][physA] = (arow_)[3 * (astride_)]; Bs[buf][rbase_ + 3][physB] = rb3; \
    As[buf][rbase_ + 4][physA] = (arow_)[4 * (astride_)]; Bs[buf][rbase_ + 4][physB] = rb4; \
    As[buf][rbase_ + 5][physA] = (arow_)[5 * (astride_)]; Bs[buf][rbase_ + 5][physB] = rb5; \
    As[buf][rbase_ + 6][physA] = (arow_)[6 * (astride_)]; Bs[buf][rbase_ + 6][physB] = rb6; \
    As[buf][rbase_ + 7][physA] = (arow_)[7 * (astride_)]; Bs[buf][rbase_ + 7][physB] = rb7; \
} while (0)

#define EPI(M,N) do { \
    int mrow = m0 + wm + M*16 + g; \
    int nc = n0 + wn + N*8 + tg*2; \
    if (nc < HW) { \
        if (MODE == 0) { \
            float v0 = c##M##N##x, v1 = c##M##N##y, v2 = c##M##N##z, v3 = c##M##N##w; \
            Yb[(size_t)mrow * HW + nc] = v0; \
            Yb[(size_t)(mrow + 8) * HW + nc] = v2; \
            ((__half*)g_F1h)[((size_t)(mrow >> 1)) * (2 * HW) + 2 * nc + (mrow & 1)] = __float2half_rn(fmaxf(v0, 0.f)); \
            ((__half*)g_F1h)[((size_t)((mrow + 8) >> 1)) * (2 * HW) + 2 * nc + ((mrow + 8) & 1)] = __float2half_rn(fmaxf(v2, 0.f)); \
            if (nc + 1 < HW) { \
                Yb[(size_t)mrow * HW + nc + 1] = v1; \
                Yb[(size_t)(mrow + 8) * HW + nc + 1] = v3; \
                ((__half*)g_F1h)[((size_t)(mrow >> 1)) * (2 * HW) + 2 * (nc + 1) + (mrow & 1)] = __float2half_rn(fmaxf(v1, 0.f)); \
                ((__half*)g_F1h)[((size_t)((mrow + 8) >> 1)) * (2 * HW) + 2 * (nc + 1) + ((mrow + 8) & 1)] = __float2half_rn(fmaxf(v3, 0.f)); \
            } \
        } else { \
            float ra_ = Rb[(size_t)mrow * HW + nc]; \
            float rb_ = (nc + 1 < HW) ? Rb[(size_t)mrow * HW + nc + 1] : 0.f; \
            float rc_ = Rb[(size_t)(mrow + 8) * HW + nc]; \
            float rd_ = (nc + 1 < HW) ? Rb[(size_t)(mrow + 8) * HW + nc + 1] : 0.f; \
            F2hz[(size_t)mrow * F2W + (nc >> 1)] = packh2(fmaxf(c##M##N##x + ra_, 0.f), fmaxf(c##M##N##y + rb_, 0.f)); \
            F2hz[(size_t)(mrow + 8) * F2W + (nc >> 1)] = packh2(fmaxf(c##M##N##z + rc_, 0.f), fmaxf(c##M##N##w + rd_, 0.f)); \
        } \
    } \
} while (0)

template <int MODE>
__global__ void __launch_bounds__(256) k_mma(const float* __restrict__ Kin) {
    __shared__ __align__(16) uint32_t As[2][16][RA];
    __shared__ __align__(16) uint32_t Bs[2][16][RB];
    int tid = threadIdx.x;
    int n0 = blockIdx.x * 128, m0 = blockIdx.y * 128;
    int z = blockIdx.z;

    int col = tid & 127;
    int krow0 = tid >> 7;         // 0 or 1
    int n = n0 + col;
    bool nvalid = n < HW;
    int ny = n / WW, nx = n - ny * WW;

    int physA = ((((col >> 6) * 2 + ((col >> 3) & 1)) * 8 + (col & 7)) * 4) + ((col >> 4) & 3);
    int physB = (col >> 5) * 32 + (col & 7) * 4 + ((col >> 3) & 3);

    int warp = tid >> 5, lane = tid & 31;
    int wm = (warp & 1) * 64, wn = (warp >> 1) * 32;
    int g = lane >> 2, tg = lane & 3;

    int aix = (warp & 1) * 64 + g * 4;
    int bix = (warp >> 1) * 32 + g * 4;

    float* Yb = g_F1;
    const float* Rb = g_F1 + (size_t)z * DK * HW;
    uint32_t* F2hz = g_F2h + (size_t)z * DK * F2W;

    DECL_ACC(0,0); DECL_ACC(0,1); DECL_ACC(0,2); DECL_ACC(0,3);
    DECL_ACC(1,0); DECL_ACC(1,1); DECL_ACC(1,2); DECL_ACC(1,3);
    DECL_ACC(2,0); DECL_ACC(2,1); DECL_ACC(2,2); DECL_ACC(2,3);
    DECL_ACC(3,0); DECL_ACC(3,1); DECL_ACC(3,2); DECL_ACC(3,3);

    uint32_t rb0, rb1, rb2, rb3, rb4, rb5, rb6, rb7;

    if (MODE == 0) {
        const int S = 16;
        LDSTAGEB0(0);
        for (int s = 0; s < S; s++) {
            int buf = s & 1;
            const uint32_t* arow_ = g_Wt1p + (size_t)(s * 16 + krow0 * 8) * 1024 + m0 + col;
            STSTAGE_COMMON(buf, arow_, 1024);
            __syncthreads();
            if (s + 1 < S) LDSTAGEB0(s + 1);
            MMA_SLICE(buf, 0);
            MMA_SLICE(buf, 8);
        }
    } else {
        const int S = 9 * 16;
        const uint32_t* F1hz = g_F1h + (size_t)z * 256 * HW;
        LDSTAGEB1(0);
        for (int s = 0; s < S; s++) {
            int buf = s & 1;
            int t_ = s >> 4, kc32_ = s & 15;
            const uint32_t* arow_ = g_Wt2p + ((size_t)(z * 9 + t_) * 256 + kc32_ * 16 + krow0 * 8) * 512 + m0 + col;
            STSTAGE_COMMON(buf, arow_, 512);
            __syncthreads();
            if (s + 1 < S) LDSTAGEB1(s + 1);
            MMA_SLICE(buf, 0);
            MMA_SLICE(buf, 8);
        }
    }

    EPI(0,0); EPI(0,1); EPI(0,2); EPI(0,3);
    EPI(1,0); EPI(1,1); EPI(1,2); EPI(1,3);
    EPI(2,0); EPI(2,1); EPI(2,2); EPI(2,3);
    EPI(3,0); EPI(3,1); EPI(3,2); EPI(3,3);
}

// ---------------- F3 partials: half2 F2, c-chunks of 32 (16 chunks) ----------------
__global__ void k_f3p(const float* __restrict__ amp3, const float* __restrict__ pha3) {
    __shared__ float ws[NH * 32];
    int tid = threadIdx.x;
    int c0 = blockIdx.y * 32;
    int br = blockIdx.z;
    const float* W3 = br ? pha3 : amp3;
    const uint32_t* F2b = g_F2h + (size_t)br * DK * F2W;
    for (int i = tid; i < NH * 32; i += 256) {
        int h = i >> 5, c = i & 31;
        ws[i] = W3[h * DK + c0 + c];
    }
    __syncthreads();
    int sp = blockIdx.x * 256 + tid;
    if (sp >= F2W) return;
    int s0 = 2 * sp;
    float acc0[NH] = {}, acc1[NH] = {};
    for (int c = 0; c < 32; c++) {
        uint32_t u = F2b[(size_t)(c0 + c) * F2W + sp];
        __half2 hv = *reinterpret_cast<const __half2*>(&u);
        float2 f = __half22float2(hv);
        #pragma unroll
        for (int h = 0; h < NH; h++) {
            acc0[h] += ws[h * 32 + c] * f.x;
            acc1[h] += ws[h * 32 + c] * f.y;
        }
    }
    float* outp = g_F3p + ((size_t)br * 16 + blockIdx.y) * NH * HW;
    #pragma unroll
    for (int h = 0; h < NH; h++) {
        outp[h * HW + s0] = acc0[h];
        if (s0 + 1 < HW) outp[h * HW + s0 + 1] = acc1[h];
    }
}

__global__ void k_f3red() {
    int idx = blockIdx.x * 256 + threadIdx.x;
    if (idx >= NH * HW) return;
    int br = blockIdx.y;
    const float* p = g_F3p + (size_t)br * 16 * NH * HW;
    float s = 0.f;
    #pragma unroll
    for (int i = 0; i < 16; i++) s += p[i * NH * HW + idx];
    g_F3[br * NH * HW + idx] = fmaxf(s, 0.f);
}

// ---------------- down-proj (warp per output j) ----------------
__global__ void k_down(const float* __restrict__ Wd1, const float* __restrict__ bd1,
                       const float* __restrict__ Wd2, const float* __restrict__ bd2) {
    int warp = threadIdx.x >> 5, lane = threadIdx.x & 31;
    int j = blockIdx.x * 8 + warp;
    int br = blockIdx.y;
    if (j >= HRW) return;
    const float* Wd = br ? Wd2 : Wd1;
    const float* bd = br ? bd2 : bd1;
    const float* F3b = g_F3 + br * NH * HW;
    const float* wr = Wd + (size_t)j * HW;
    float acc[NH] = {};
    for (int s = lane; s < HW; s += 32) {
        float wv = wr[s];
        #pragma unroll
        for (int h = 0; h < NH; h++) acc[h] += wv * F3b[h * HW + s];
    }
    #pragma unroll
    for (int h = 0; h < NH; h++) {
        #pragma unroll
        for (int o = 16; o > 0; o >>= 1) acc[h] += __shfl_down_sync(0xffffffffu, acc[h], o);
    }
    if (lane == 0) {
        float b = bd[j];
        #pragma unroll
        for (int h = 0; h < NH; h++) g_filt[br][h * HRW + j] = acc[h] + b;
    }
}

// ---------------- FFT chain (A0 reduction fused into row FFT) ----------------
__global__ void k_fftrow() {
    int hy = blockIdx.x;
    int h = hy / HH, y = hy % HH;
    __shared__ float row[HH], twc[HH], tws[HH];
    int tid = threadIdx.x;  // 64
    for (int i = tid; i < HH; i += 64) {
        float s = 0.f;
        #pragma unroll
        for (int p = 0; p < 8; p++) s += g_A0p[p * NH * HW + h * HW + y * WW + i];
        row[i] = (s + g_qb[h]) * 0.04419417382415922f;
        float sv, cv;
        sincosf(TWO_PI * (float)i / 65.f, &sv, &cv);
        twc[i] = cv; tws[i] = sv;
    }
    __syncthreads();
    if (tid < RW) {
        float re = 0.f, im = 0.f;
        for (int x = 0; x < HH; x++) {
            int t = (tid * x) % 65;
            re += row[x] * twc[t];
            im -= row[x] * tws[t];
        }
        g_Fr[h * HRW + y * RW + tid] = make_float2(re, im);
    }
}

__global__ void k_fftcol_mod() {
    __shared__ float twc[HH], tws[HH];
    for (int i = threadIdx.x; i < HH; i += 256) {
        float sv, cv;
        sincosf(TWO_PI * (float)i / 65.f, &sv, &cv);
        twc[i] = cv; tws[i] = sv;
    }
    __syncthreads();
    int idx = blockIdx.x * 256 + threadIdx.x;
    if (idx >= NH * HRW) return;
    int h = idx / HRW, r = idx % HRW;
    int ky = r / RW, kx = r % RW;
    const float2* fr = g_Fr + h * HRW + kx;
    float re = 0.f, im = 0.f;
    for (int y = 0; y < HH; y++) {
        int t = (ky * y) % 65;
        float c = twc[t], s = tws[t];
        float2 f = fr[y * RW];
        re += f.x * c + f.y * s;
        im += f.y * c - f.x * s;
    }
    float mag = sqrtf(re * re + im * im);
    float ang = atan2f(im, re);
    float a = g_filt[0][idx] * mag;
    float p = g_filt[1][idx] * ang;
    float sp, cp;
    sincosf(p, &sp, &cp);
    g_Af[idx] = make_float2(a * cp, a * sp);
}

__global__ void k_invcol() {
    __shared__ float twc[HH], tws[HH];
    for (int i = threadIdx.x; i < HH; i += 256) {
        float sv, cv;
        sincosf(TWO_PI * (float)i / 65.f, &sv, &cv);
        twc[i] = cv; tws[i] = sv;
    }
    __syncthreads();
    int idx = blockIdx.x * 256 + threadIdx.x;
    if (idx >= NH * HRW) return;
    int h = idx / HRW, r = idx % HRW;
    int y = r / RW, kx = r % RW;
    const float2* af = g_Af + h * HRW + kx;
    float re = 0.f, im = 0.f;
    for (int ky = 0; ky < HH; ky++) {
        int t = (ky * y) % 65;
        float c = twc[t], s = tws[t];
        float2 f = af[ky * RW];
        re += f.x * c - f.y * s;
        im += f.y * c + f.x * s;
    }
    g_Gr[idx] = make_float2(re * (1.f / 65.f), im * (1.f / 65.f));
}

__global__ void k_invrow() {
    __shared__ float twc[HH], tws[HH];
    for (int i = threadIdx.x; i < HH; i += 256) {
        float sv, cv;
        sincosf(TWO_PI * (float)i / 65.f, &sv, &cv);
        twc[i] = cv; tws[i] = sv;
    }
    __syncthreads();
    int idx = blockIdx.x * 256 + threadIdx.x;
    if (idx >= NH * HW) return;
    int h = idx / HW, s = idx % HW;
    int y = s / WW, x = s % WW;
    const float2* gp = g_Gr + h * HRW + y * RW;
    float acc = gp[0].x;
    for (int k = 1; k < RW; k++) {
        int t = (k * x) % 65;
        acc += 2.f * (gp[k].x * twc[t] - gp[k].y * tws[t]);
    }
    g_A[idx] = acc * (1.f / 65.f);
}

// ---------------- softmax per head (1024 threads) ----------------
__global__ void k_softmax() {
    int h = blockIdx.x, tid = threadIdx.x;
    __shared__ float red[1024];
    const float* a = g_A + h * HW;
    float* p = g_P + h * HW;
    float mx = -3.4e38f;
    for (int s = tid; s < HW; s += 1024) mx = fmaxf(mx, a[s]);
    red[tid] = mx;
    __syncthreads();
    for (int st = 512; st > 0; st >>= 1) {
        if (tid < st) red[tid] = fmaxf(red[tid], red[tid + st]);
        __syncthreads();
    }
    mx = red[0];
    __syncthreads();
    float sum = 0.f;
    for (int s = tid; s < HW; s += 1024) {
        float e = expf(a[s] - mx);
        p[s] = e;
        sum += e;
    }
    red[tid] = sum;
    __syncthreads();
    for (int st = 512; st > 0; st >>= 1) {
        if (tid < st) red[tid] += red[tid + st];
        __syncthreads();
    }
    float inv = 1.f / red[0];
    for (int s = tid; s < HW; s += 1024) p[s] *= inv;
}

// ---------------- m[h,c] = sum_s P[h,s]*K[c,s] ----------------
__global__ void k_m(const float* __restrict__ K) {
    int c = blockIdx.x * 8 + (threadIdx.x >> 5);
    int lane = threadIdx.x & 31;
    const float* kr = K + c * HW;
    float acc[NH] = {};
    for (int s = lane; s < HW; s += 32) {
        float kv = kr[s];
        #pragma unroll
        for (int h = 0; h < NH; h++) acc[h] += kv * g_P[h * HW + s];
    }
    #pragma unroll
    for (int h = 0; h < NH; h++) {
        #pragma unroll
        for (int o = 16; o > 0; o >>= 1) acc[h] += __shfl_down_sync(0xffffffffu, acc[h], o);
    }
    if (lane == 0) {
        #pragma unroll
        for (int h = 0; h < NH; h++) g_m[h * DK + c] = acc[h];
    }
}

__global__ void k_vproj(const float* __restrict__ Wv, const float* __restrict__ bv) {
    int r = blockIdx.x * 8 + (threadIdx.x >> 5);
    int lane = threadIdx.x & 31;
    int h = r >> 9;
    const float* mr = g_m + (h << 9);
    const float* wr = Wv + r * DK;
    float acc = 0.f;
    for (int c = lane; c < DK; c += 32) acc += wr[c] * mr[c];
    #pragma unroll
    for (int o = 16; o > 0; o >>= 1) acc += __shfl_down_sync(0xffffffffu, acc, o);
    if (lane == 0) g_x[r] = acc + bv[r];
}

__global__ void k_out(const float* __restrict__ Wo, const float* __restrict__ bo,
                      float* __restrict__ out) {
    int r = blockIdx.x * 8 + (threadIdx.x >> 5);
    int lane = threadIdx.x & 31;
    const float* wr = Wo + r * DHID;
    float acc = 0.f;
    for (int j = lane; j < DHID; j += 32) acc += wr[j] * g_x[j];
    #pragma unroll
    for (int o = 16; o > 0; o >>= 1) acc += __shfl_down_sync(0xffffffffu, acc, o);
    if (lane == 0) out[r] = acc + bo[r];
}

extern "C" void kernel_launch(void* const* d_in, const int* in_sizes, int n_in,
                              void* d_out, int out_size) {
    const float* Q    = (const float*)d_in[0];
    const float* K    = (const float*)d_in[1];
    const float* Wq   = (const float*)d_in[2];
    const float* bq   = (const float*)d_in[3];
    const float* Wk   = (const float*)d_in[4];
    const float* bk   = (const float*)d_in[5];
    const float* Wv   = (const float*)d_in[6];
    const float* bv   = (const float*)d_in[7];
    const float* Wo   = (const float*)d_in[8];
    const float* bo   = (const float*)d_in[9];
    const float* amp1 = (const float*)d_in[10];
    const float* amp2 = (const float*)d_in[11];
    const float* amp3 = (const float*)d_in[12];
    const float* pha1 = (const float*)d_in[13];
    const float* pha2 = (const float*)d_in[14];
    const float* pha3 = (const float*)d_in[15];
    const float* Wd1  = (const float*)d_in[16];
    const float* bd1  = (const float*)d_in[17];
    const float* Wd2  = (const float*)d_in[18];
    const float* bd2  = (const float*)d_in[19];
    float* out = (float*)d_out;

    // conv path first: positions k_mma<1> at launch #4 (where ncu samples)
    k_tr1<<<1024, 256>>>(amp1, pha1);                                    // 1
    k_tr2<<<dim3(18, 16, 16), dim3(32, 8)>>>(amp2, pha2);                // 2
    k_mma<0><<<dim3(34, 8, 1), 256>>>(K);                                // 3
    k_mma<1><<<dim3(34, 4, 2), 256>>>(K);                                // 4

    // attention-score path
    k_qproj<<<512, 256>>>(Q, Wq, bq);
    k_qb<<<1, 256>>>(bk);
    k_u<<<dim3(8, 8), 512>>>(Wk);
    k_A0p<<<dim3(17, 8), 256>>>(K);

    k_f3p<<<dim3(9, 16, 2), 256>>>(amp3, pha3);
    k_f3red<<<dim3(133, 2), 256>>>();
    k_down<<<dim3(269, 2), 256>>>(Wd1, bd1, Wd2, bd2);

    // spectral filtering (A0 reduce fused into fftrow)
    k_fftrow<<<NH * HH, 64>>>();
    k_fftcol_mod<<<68, 256>>>();
    k_invcol<<<68, 256>>>();
    k_invrow<<<133, 256>>>();
    k_softmax<<<NH, 1024>>>();

    // output path
    k_m<<<64, 256>>>(K);
    k_vproj<<<512, 256>>>(Wv, bv);
    k_out<<<64, 256>>>(Wo, bo, out);
}

// round 17
// speedup vs baseline: 1.0536x; 1.0446x over previous
#include <cuda_runtime.h>
#include <cuda_fp16.h>
#include <math.h>
#include <stdint.h>

#define HH 65
#define WW 65
#define HW 4225
#define NH 8
#define DK 512
#define RW 33
#define HRW 2145
#define DHID 4096
#define F2W 2113   // words per F2h row ((4225+1)/2)

// ---------------- scratch (device globals) ----------------
__device__ float g_q[DHID];
__device__ float g_up[8 * 4096];
__device__ float g_qb[NH];
__device__ float g_A0p[8 * NH * HW];
__device__ uint32_t g_Wt1p[256 * 1024];        // half2(k,k+1), [kp][br*512+o]
__device__ uint32_t g_Wt2p[2 * 9 * 256 * 512]; // half2, [(bt*256+kpg)][o]
__device__ float g_F1[2 * DK * HW];            // fp32 (for residual)
__device__ uint32_t g_F1h[2 * 256 * HW];       // half2 of relu(F1), k-paired
__device__ uint32_t g_F2h[2 * DK * F2W];       // half2 of relu(F2), s-paired
__device__ float g_F3p[2 * 16 * NH * HW];
__device__ float g_F3[2 * NH * HW];
__device__ float g_filt[2][NH * HRW];
__device__ float2 g_Fr[NH * HRW];
__device__ float2 g_Af[NH * HRW];
__device__ float2 g_Gr[NH * HRW];
__device__ float g_A[NH * HW];
__device__ float g_P[NH * HW];
__device__ float g_m[NH * DK];
__device__ float g_x[DHID];

#define TWO_PI 6.28318530717958647692f

__device__ __forceinline__ uint32_t packh2(float lo, float hi) {
    uint32_t l = __half_as_ushort(__float2half_rn(lo));
    uint32_t h = __half_as_ushort(__float2half_rn(hi));
    return l | (h << 16);
}

__device__ __forceinline__ void mma_f16(
    float& c0, float& c1, float& c2, float& c3,
    uint32_t a0, uint32_t a1, uint32_t a2, uint32_t a3,
    uint32_t b0, uint32_t b1) {
    asm volatile(
        "mma.sync.aligned.m16n8k16.row.col.f32.f16.f16.f32 "
        "{%0,%1,%2,%3},{%4,%5,%6,%7},{%8,%9},{%0,%1,%2,%3};"
        : "+f"(c0), "+f"(c1), "+f"(c2), "+f"(c3)
        : "r"(a0), "r"(a1), "r"(a2), "r"(a3), "r"(b0), "r"(b1));
}

// ---------------- q = Wq @ Q + bq ----------------
__global__ void k_qproj(const float* __restrict__ Q, const float* __restrict__ Wq,
                        const float* __restrict__ bq) {
    int r = blockIdx.x * 8 + (threadIdx.x >> 5);
    int lane = threadIdx.x & 31;
    const float* wr = Wq + r * DK;
    float acc = 0.f;
    for (int c = lane; c < DK; c += 32) acc += wr[c] * Q[c];
    #pragma unroll
    for (int o = 16; o > 0; o >>= 1) acc += __shfl_down_sync(0xffffffffu, acc, o);
    if (lane == 0) g_q[r] = acc + bq[r];
}

// ---------------- qb[h] = q_h . bk_h ----------------
__global__ void k_qb(const float* __restrict__ bk) {
    int h = threadIdx.x >> 5, lane = threadIdx.x & 31;
    float acc = 0.f;
    for (int d = lane; d < DK; d += 32) acc += g_q[h * DK + d] * bk[h * DK + d];
    #pragma unroll
    for (int o = 16; o > 0; o >>= 1) acc += __shfl_down_sync(0xffffffffu, acc, o);
    if (lane == 0) g_qb[h] = acc;
}

// ---------------- u partials ----------------
__global__ void k_u(const float* __restrict__ Wk) {
    int h = blockIdx.x, p = blockIdx.y;
    int tid = threadIdx.x;  // 512
    __shared__ float qs[64];
    if (tid < 64) qs[tid] = g_q[h * DK + p * 64 + tid];
    __syncthreads();
    float acc = 0.f;
    const float* wb = Wk + h * DK * DK + (p * 64) * DK + tid;
    #pragma unroll 8
    for (int d = 0; d < 64; d++) acc += wb[d * DK] * qs[d];
    g_up[p * 4096 + h * DK + tid] = acc;
}

// ---------------- A0 partials over c-chunks of 64 ----------------
__global__ void k_A0p(const float* __restrict__ K) {
    __shared__ float us[NH * 64];
    int tid = threadIdx.x;
    int c0 = blockIdx.y * 64;
    for (int i = tid; i < NH * 64; i += 256) {
        int h = i >> 6, c = i & 63;
        float s = 0.f;
        #pragma unroll
        for (int p = 0; p < 8; p++) s += g_up[p * 4096 + h * DK + c0 + c];
        us[i] = s;
    }
    __syncthreads();
    int s = blockIdx.x * 256 + tid;
    if (s >= HW) return;
    float acc[NH] = {};
    for (int c = 0; c < 64; c++) {
        float kv = K[(c0 + c) * HW + s];
        #pragma unroll
        for (int h = 0; h < NH; h++) acc[h] += us[h * 64 + c] * kv;
    }
    #pragma unroll
    for (int h = 0; h < NH; h++) g_A0p[blockIdx.y * NH * HW + h * HW + s] = acc[h];
}

// ---------------- weight prep: pack half2 along k ----------------
__global__ void k_tr1(const float* __restrict__ amp1, const float* __restrict__ pha1) {
    int idx = blockIdx.x * 256 + threadIdx.x;   // 2*131072
    int br = idx >> 17;
    int r = idx & 131071;
    int kp = r >> 9, o = r & 511;
    const float* src = br ? pha1 : amp1;
    float lo = src[o * DK + 2 * kp];
    float hi = src[o * DK + 2 * kp + 1];
    g_Wt1p[kp * 1024 + br * 512 + o] = packh2(lo, hi);
}

__global__ void k_tr2(const float* __restrict__ amp2, const float* __restrict__ pha2) {
    __shared__ float tile[32][33];
    int bt = blockIdx.x;           // br*9 + t
    int br = bt / 9, t = bt % 9;
    const float* src = br ? pha2 : amp2;
    int o0 = blockIdx.y * 32, i0 = blockIdx.z * 32;
    int tx = threadIdx.x, ty = threadIdx.y;
    #pragma unroll
    for (int r = 0; r < 32; r += 8)
        tile[ty + r][tx] = src[((o0 + ty + r) * DK + i0 + tx) * 9 + t];
    __syncthreads();
    int tid2 = ty * 32 + tx;
    #pragma unroll
    for (int p = 0; p < 2; p++) {
        int wi = tid2 + p * 256;          // 0..511
        int kp_l = wi >> 5, o_l = wi & 31;
        int kpg = (i0 >> 1) + kp_l;
        uint32_t v = packh2(tile[o_l][2 * kp_l], tile[o_l][2 * kp_l + 1]);
        g_Wt2p[((size_t)bt * 256 + kpg) * 512 + o0 + o_l] = v;
    }
}

// ---------------- fp16 tensor-core GEMM / implicit conv ----------------
#define RA 132
#define RB 136

#define DECL_ACC(M,N) float c##M##N##x = 0.f, c##M##N##y = 0.f, c##M##N##z = 0.f, c##M##N##w = 0.f

#define MMA_SLICE(buf, ro) do { \
    uint4 a00 = *(const uint4*)&As[buf][(ro) + tg][aix]; \
    uint4 a01 = *(const uint4*)&As[buf][(ro) + tg][aix + 32]; \
    uint4 a10 = *(const uint4*)&As[buf][(ro) + tg + 4][aix]; \
    uint4 a11 = *(const uint4*)&As[buf][(ro) + tg + 4][aix + 32]; \
    uint4 b0v = *(const uint4*)&Bs[buf][(ro) + tg][bix]; \
    uint4 b1v = *(const uint4*)&Bs[buf][(ro) + tg + 4][bix]; \
    mma_f16(c00x,c00y,c00z,c00w, a00.x,a01.x,a10.x,a11.x, b0v.x,b1v.x); \
    mma_f16(c01x,c01y,c01z,c01w, a00.x,a01.x,a10.x,a11.x, b0v.y,b1v.y); \
    mma_f16(c02x,c02y,c02z,c02w, a00.x,a01.x,a10.x,a11.x, b0v.z,b1v.z); \
    mma_f16(c03x,c03y,c03z,c03w, a00.x,a01.x,a10.x,a11.x, b0v.w,b1v.w); \
    mma_f16(c10x,c10y,c10z,c10w, a00.y,a01.y,a10.y,a11.y, b0v.x,b1v.x); \
    mma_f16(c11x,c11y,c11z,c11w, a00.y,a01.y,a10.y,a11.y, b0v.y,b1v.y); \
    mma_f16(c12x,c12y,c12z,c12w, a00.y,a01.y,a10.y,a11.y, b0v.z,b1v.z); \
    mma_f16(c13x,c13y,c13z,c13w, a00.y,a01.y,a10.y,a11.y, b0v.w,b1v.w); \
    mma_f16(c20x,c20y,c20z,c20w, a00.z,a01.z,a10.z,a11.z, b0v.x,b1v.x); \
    mma_f16(c21x,c21y,c21z,c21w, a00.z,a01.z,a10.z,a11.z, b0v.y,b1v.y); \
    mma_f16(c22x,c22y,c22z,c22w, a00.z,a01.z,a10.z,a11.z, b0v.z,b1v.z); \
    mma_f16(c23x,c23y,c23z,c23w, a00.z,a01.z,a10.z,a11.z, b0v.w,b1v.w); \
    mma_f16(c30x,c30y,c30z,c30w, a00.w,a01.w,a10.w,a11.w, b0v.x,b1v.x); \
    mma_f16(c31x,c31y,c31z,c31w, a00.w,a01.w,a10.w,a11.w, b0v.y,b1v.y); \
    mma_f16(c32x,c32y,c32z,c32w, a00.w,a01.w,a10.w,a11.w, b0v.z,b1v.z); \
    mma_f16(c33x,c33y,c33z,c33w, a00.w,a01.w,a10.w,a11.w, b0v.w,b1v.w); \
} while (0)

#define LDSTAGEB1(s) do { \
    int t_ = (s) >> 4; \
    int kc32_ = (s) & 15; \
    int dy_ = t_ / 3 - 1, dx_ = t_ % 3 - 1; \
    int yy_ = ny + dy_, xx_ = nx + dx_; \
    bool ok_ = nvalid && (unsigned)yy_ < HH && (unsigned)xx_ < WW; \
    int src_ = ok_ ? (yy_ * WW + xx_) : 0; \
    const uint32_t* brow_ = F1hz + (size_t)(kc32_ * 16 + krow0 * 8) * HW + src_; \
    rb0 = ok_ ? brow_[0 * (size_t)HW] : 0u; \
    rb1 = ok_ ? brow_[1 * (size_t)HW] : 0u; \
    rb2 = ok_ ? brow_[2 * (size_t)HW] : 0u; \
    rb3 = ok_ ? brow_[3 * (size_t)HW] : 0u; \
    rb4 = ok_ ? brow_[4 * (size_t)HW] : 0u; \
    rb5 = ok_ ? brow_[5 * (size_t)HW] : 0u; \
    rb6 = ok_ ? brow_[6 * (size_t)HW] : 0u; \
    rb7 = ok_ ? brow_[7 * (size_t)HW] : 0u; \
} while (0)

#define LDSTAGEB0(s) do { \
    int kb_ = ((s) * 16 + krow0 * 8) * 2; \
    if (nvalid) { \
        rb0 = packh2(Kin[(size_t)(kb_ + 0) * HW + n],  Kin[(size_t)(kb_ + 1) * HW + n]); \
        rb1 = packh2(Kin[(size_t)(kb_ + 2) * HW + n],  Kin[(size_t)(kb_ + 3) * HW + n]); \
        rb2 = packh2(Kin[(size_t)(kb_ + 4) * HW + n],  Kin[(size_t)(kb_ + 5) * HW + n]); \
        rb3 = packh2(Kin[(size_t)(kb_ + 6) * HW + n],  Kin[(size_t)(kb_ + 7) * HW + n]); \
        rb4 = packh2(Kin[(size_t)(kb_ + 8) * HW + n],  Kin[(size_t)(kb_ + 9) * HW + n]); \
        rb5 = packh2(Kin[(size_t)(kb_ + 10) * HW + n], Kin[(size_t)(kb_ + 11) * HW + n]); \
        rb6 = packh2(Kin[(size_t)(kb_ + 12) * HW + n], Kin[(size_t)(kb_ + 13) * HW + n]); \
        rb7 = packh2(Kin[(size_t)(kb_ + 14) * HW + n], Kin[(size_t)(kb_ + 15) * HW + n]); \
    } else { rb0=rb1=rb2=rb3=rb4=rb5=rb6=rb7=0u; } \
} while (0)

#define STSTAGE_COMMON(buf, arow_, astride_) do { \
    int rbase_ = krow0 * 8; \
    As[buf][rbase_ + 0][physA] = (arow_)[0 * (astride_)]; Bs[buf][rbase_ + 0][physB] = rb0; \
    As[buf][rbase_ + 1][physA] = (arow_)[1 * (astride_)]; Bs[buf][rbase_ + 1][physB] = rb1; \
    As[buf][rbase_ + 2][physA] = (arow_)[2 * (astride_)]; Bs[buf][rbase_ + 2][physB] = rb2; \
    As[buf][rbase_ + 3][physA] = (arow_)[3 * (astride_)]; Bs[buf][rbase_ + 3][physB] = rb3; \
    As[buf][rbase_ + 4][physA] = (arow_)[4 * (astride_)]; Bs[buf][rbase_ + 4][physB] = rb4; \
    As[buf][rbase_ + 5][physA] = (arow_)[5 * (astride_)]; Bs[buf][rbase_ + 5][physB] = rb5; \
    As[buf][rbase_ + 6][physA] = (arow_)[6 * (astride_)]; Bs[buf][rbase_ + 6][physB] = rb6; \
    As[buf][rbase_ + 7][physA] = (arow_)[7 * (astride_)]; Bs[buf][rbase_ + 7][physB] = rb7; \
} while (0)

#define EPI(M,N) do { \
    int mrow = m0 + wm + M*16 + g; \
    int nc = n0 + wn + N*8 + tg*2; \
    if (nc < HW) { \
        if (MODE == 0) { \
            float v0 = c##M##N##x, v1 = c##M##N##y, v2 = c##M##N##z, v3 = c##M##N##w; \
            Yb[(size_t)mrow * HW + nc] = v0; \
            Yb[(size_t)(mrow + 8) * HW + nc] = v2; \
            ((__half*)g_F1h)[((size_t)(mrow >> 1)) * (2 * HW) + 2 * nc + (mrow & 1)] = __float2half_rn(fmaxf(v0, 0.f)); \
            ((__half*)g_F1h)[((size_t)((mrow + 8) >> 1)) * (2 * HW) + 2 * nc + ((mrow + 8) & 1)] = __float2half_rn(fmaxf(v2, 0.f)); \
            if (nc + 1 < HW) { \
                Yb[(size_t)mrow * HW + nc + 1] = v1; \
                Yb[(size_t)(mrow + 8) * HW + nc + 1] = v3; \
                ((__half*)g_F1h)[((size_t)(mrow >> 1)) * (2 * HW) + 2 * (nc + 1) + (mrow & 1)] = __float2half_rn(fmaxf(v1, 0.f)); \
                ((__half*)g_F1h)[((size_t)((mrow + 8) >> 1)) * (2 * HW) + 2 * (nc + 1) + ((mrow + 8) & 1)] = __float2half_rn(fmaxf(v3, 0.f)); \
            } \
        } else { \
            float ra_ = Rb[(size_t)mrow * HW + nc]; \
            float rb_ = (nc + 1 < HW) ? Rb[(size_t)mrow * HW + nc + 1] : 0.f; \
            float rc_ = Rb[(size_t)(mrow + 8) * HW + nc]; \
            float rd_ = (nc + 1 < HW) ? Rb[(size_t)(mrow + 8) * HW + nc + 1] : 0.f; \
            F2hz[(size_t)mrow * F2W + (nc >> 1)] = packh2(fmaxf(c##M##N##x + ra_, 0.f), fmaxf(c##M##N##y + rb_, 0.f)); \
            F2hz[(size_t)(mrow + 8) * F2W + (nc >> 1)] = packh2(fmaxf(c##M##N##z + rc_, 0.f), fmaxf(c##M##N##w + rd_, 0.f)); \
        } \
    } \
} while (0)

template <int MODE>
__global__ void __launch_bounds__(256) k_mma(const float* __restrict__ Kin) {
    __shared__ __align__(16) uint32_t As[2][16][RA];
    __shared__ __align__(16) uint32_t Bs[2][16][RB];
    int tid = threadIdx.x;
    int n0 = blockIdx.x * 128, m0 = blockIdx.y * 128;
    int z = blockIdx.z;

    int col = tid & 127;
    int krow0 = tid >> 7;         // 0 or 1
    int n = n0 + col;
    bool nvalid = n < HW;
    int ny = n / WW, nx = n - ny * WW;

    int physA = ((((col >> 6) * 2 + ((col >> 3) & 1)) * 8 + (col & 7)) * 4) + ((col >> 4) & 3);
    int physB = (col >> 5) * 32 + (col & 7) * 4 + ((col >> 3) & 3);

    int warp = tid >> 5, lane = tid & 31;
    int wm = (warp & 1) * 64, wn = (warp >> 1) * 32;
    int g = lane >> 2, tg = lane & 3;

    int aix = (warp & 1) * 64 + g * 4;
    int bix = (warp >> 1) * 32 + g * 4;

    float* Yb = g_F1;
    const float* Rb = g_F1 + (size_t)z * DK * HW;
    uint32_t* F2hz = g_F2h + (size_t)z * DK * F2W;

    DECL_ACC(0,0); DECL_ACC(0,1); DECL_ACC(0,2); DECL_ACC(0,3);
    DECL_ACC(1,0); DECL_ACC(1,1); DECL_ACC(1,2); DECL_ACC(1,3);
    DECL_ACC(2,0); DECL_ACC(2,1); DECL_ACC(2,2); DECL_ACC(2,3);
    DECL_ACC(3,0); DECL_ACC(3,1); DECL_ACC(3,2); DECL_ACC(3,3);

    uint32_t rb0, rb1, rb2, rb3, rb4, rb5, rb6, rb7;

    if (MODE == 0) {
        const int S = 16;
        LDSTAGEB0(0);
        for (int s = 0; s < S; s++) {
            int buf = s & 1;
            const uint32_t* arow_ = g_Wt1p + (size_t)(s * 16 + krow0 * 8) * 1024 + m0 + col;
            STSTAGE_COMMON(buf, arow_, 1024);
            __syncthreads();
            if (s + 1 < S) LDSTAGEB0(s + 1);
            MMA_SLICE(buf, 0);
            MMA_SLICE(buf, 8);
        }
    } else {
        const int S = 9 * 16;
        const uint32_t* F1hz = g_F1h + (size_t)z * 256 * HW;
        LDSTAGEB1(0);
        for (int s = 0; s < S; s++) {
            int buf = s & 1;
            int t_ = s >> 4, kc32_ = s & 15;
            const uint32_t* arow_ = g_Wt2p + ((size_t)(z * 9 + t_) * 256 + kc32_ * 16 + krow0 * 8) * 512 + m0 + col;
            STSTAGE_COMMON(buf, arow_, 512);
            __syncthreads();
            if (s + 1 < S) LDSTAGEB1(s + 1);
            MMA_SLICE(buf, 0);
            MMA_SLICE(buf, 8);
        }
    }

    EPI(0,0); EPI(0,1); EPI(0,2); EPI(0,3);
    EPI(1,0); EPI(1,1); EPI(1,2); EPI(1,3);
    EPI(2,0); EPI(2,1); EPI(2,2); EPI(2,3);
    EPI(3,0); EPI(3,1); EPI(3,2); EPI(3,3);
}

// ---------------- F3 partials: half2 F2, c-chunks of 32 (16 chunks) ----------------
__global__ void k_f3p(const float* __restrict__ amp3, const float* __restrict__ pha3) {
    __shared__ float ws[NH * 32];
    int tid = threadIdx.x;
    int c0 = blockIdx.y * 32;
    int br = blockIdx.z;
    const float* W3 = br ? pha3 : amp3;
    const uint32_t* F2b = g_F2h + (size_t)br * DK * F2W;
    for (int i = tid; i < NH * 32; i += 256) {
        int h = i >> 5, c = i & 31;
        ws[i] = W3[h * DK + c0 + c];
    }
    __syncthreads();
    int sp = blockIdx.x * 256 + tid;
    if (sp >= F2W) return;
    int s0 = 2 * sp;
    float acc0[NH] = {}, acc1[NH] = {};
    for (int c = 0; c < 32; c++) {
        uint32_t u = F2b[(size_t)(c0 + c) * F2W + sp];
        __half2 hv = *reinterpret_cast<const __half2*>(&u);
        float2 f = __half22float2(hv);
        #pragma unroll
        for (int h = 0; h < NH; h++) {
            acc0[h] += ws[h * 32 + c] * f.x;
            acc1[h] += ws[h * 32 + c] * f.y;
        }
    }
    float* outp = g_F3p + ((size_t)br * 16 + blockIdx.y) * NH * HW;
    #pragma unroll
    for (int h = 0; h < NH; h++) {
        outp[h * HW + s0] = acc0[h];
        if (s0 + 1 < HW) outp[h * HW + s0 + 1] = acc1[h];
    }
}

__global__ void k_f3red() {
    int idx = blockIdx.x * 256 + threadIdx.x;
    if (idx >= NH * HW) return;
    int br = blockIdx.y;
    const float* p = g_F3p + (size_t)br * 16 * NH * HW;
    float s = 0.f;
    #pragma unroll
    for (int i = 0; i < 16; i++) s += p[i * NH * HW + idx];
    g_F3[br * NH * HW + idx] = fmaxf(s, 0.f);
}

// ---------------- down-proj (warp per output j) ----------------
__global__ void k_down(const float* __restrict__ Wd1, const float* __restrict__ bd1,
                       const float* __restrict__ Wd2, const float* __restrict__ bd2) {
    int warp = threadIdx.x >> 5, lane = threadIdx.x & 31;
    int j = blockIdx.x * 8 + warp;
    int br = blockIdx.y;
    if (j >= HRW) return;
    const float* Wd = br ? Wd2 : Wd1;
    const float* bd = br ? bd2 : bd1;
    const float* F3b = g_F3 + br * NH * HW;
    const float* wr = Wd + (size_t)j * HW;
    float acc[NH] = {};
    for (int s = lane; s < HW; s += 32) {
        float wv = wr[s];
        #pragma unroll
        for (int h = 0; h < NH; h++) acc[h] += wv * F3b[h * HW + s];
    }
    #pragma unroll
    for (int h = 0; h < NH; h++) {
        #pragma unroll
        for (int o = 16; o > 0; o >>= 1) acc[h] += __shfl_down_sync(0xffffffffu, acc[h], o);
    }
    if (lane == 0) {
        float b = bd[j];
        #pragma unroll
        for (int h = 0; h < NH; h++) g_filt[br][h * HRW + j] = acc[h] + b;
    }
}

// ---------------- FFT chain (A0 reduction fused into row FFT) ----------------
__global__ void k_fftrow() {
    int hy = blockIdx.x;
    int h = hy / HH, y = hy % HH;
    __shared__ float row[HH], twc[HH], tws[HH];
    int tid = threadIdx.x;  // 64
    for (int i = tid; i < HH; i += 64) {
        float s = 0.f;
        #pragma unroll
        for (int p = 0; p < 8; p++) s += g_A0p[p * NH * HW + h * HW + y * WW + i];
        row[i] = (s + g_qb[h]) * 0.04419417382415922f;
        float sv, cv;
        sincosf(TWO_PI * (float)i / 65.f, &sv, &cv);
        twc[i] = cv; tws[i] = sv;
    }
    __syncthreads();
    if (tid < RW) {
        float re = 0.f, im = 0.f;
        for (int x = 0; x < HH; x++) {
            int t = (tid * x) % 65;
            re += row[x] * twc[t];
            im -= row[x] * tws[t];
        }
        g_Fr[h * HRW + y * RW + tid] = make_float2(re, im);
    }
}

__global__ void k_fftcol_mod() {
    __shared__ float twc[HH], tws[HH];
    for (int i = threadIdx.x; i < HH; i += 256) {
        float sv, cv;
        sincosf(TWO_PI * (float)i / 65.f, &sv, &cv);
        twc[i] = cv; tws[i] = sv;
    }
    __syncthreads();
    int idx = blockIdx.x * 256 + threadIdx.x;
    if (idx >= NH * HRW) return;
    int h = idx / HRW, r = idx % HRW;
    int ky = r / RW, kx = r % RW;
    const float2* fr = g_Fr + h * HRW + kx;
    float re = 0.f, im = 0.f;
    for (int y = 0; y < HH; y++) {
        int t = (ky * y) % 65;
        float c = twc[t], s = tws[t];
        float2 f = fr[y * RW];
        re += f.x * c + f.y * s;
        im += f.y * c - f.x * s;
    }
    float mag = sqrtf(re * re + im * im);
    float ang = atan2f(im, re);
    float a = g_filt[0][idx] * mag;
    float p = g_filt[1][idx] * ang;
    float sp, cp;
    sincosf(p, &sp, &cp);
    g_Af[idx] = make_float2(a * cp, a * sp);
}

__global__ void k_invcol() {
    __shared__ float twc[HH], tws[HH];
    for (int i = threadIdx.x; i < HH; i += 256) {
        float sv, cv;
        sincosf(TWO_PI * (float)i / 65.f, &sv, &cv);
        twc[i] = cv; tws[i] = sv;
    }
    __syncthreads();
    int idx = blockIdx.x * 256 + threadIdx.x;
    if (idx >= NH * HRW) return;
    int h = idx / HRW, r = idx % HRW;
    int y = r / RW, kx = r % RW;
    const float2* af = g_Af + h * HRW + kx;
    float re = 0.f, im = 0.f;
    for (int ky = 0; ky < HH; ky++) {
        int t = (ky * y) % 65;
        float c = twc[t], s = tws[t];
        float2 f = af[ky * RW];
        re += f.x * c - f.y * s;
        im += f.y * c + f.x * s;
    }
    g_Gr[idx] = make_float2(re * (1.f / 65.f), im * (1.f / 65.f));
}

__global__ void k_invrow() {
    __shared__ float twc[HH], tws[HH];
    for (int i = threadIdx.x; i < HH; i += 256) {
        float sv, cv;
        sincosf(TWO_PI * (float)i / 65.f, &sv, &cv);
        twc[i] = cv; tws[i] = sv;
    }
    __syncthreads();
    int idx = blockIdx.x * 256 + threadIdx.x;
    if (idx >= NH * HW) return;
    int h = idx / HW, s = idx % HW;
    int y = s / WW, x = s % WW;
    const float2* gp = g_Gr + h * HRW + y * RW;
    float acc = gp[0].x;
    for (int k = 1; k < RW; k++) {
        int t = (k * x) % 65;
        acc += 2.f * (gp[k].x * twc[t] - gp[k].y * tws[t]);
    }
    g_A[idx] = acc * (1.f / 65.f);
}

// ---------------- softmax per head (1024 threads) ----------------
__global__ void k_softmax() {
    int h = blockIdx.x, tid = threadIdx.x;
    __shared__ float red[1024];
    const float* a = g_A + h * HW;
    float* p = g_P + h * HW;
    float mx = -3.4e38f;
    for (int s = tid; s < HW; s += 1024) mx = fmaxf(mx, a[s]);
    red[tid] = mx;
    __syncthreads();
    for (int st = 512; st > 0; st >>= 1) {
        if (tid < st) red[tid] = fmaxf(red[tid], red[tid + st]);
        __syncthreads();
    }
    mx = red[0];
    __syncthreads();
    float sum = 0.f;
    for (int s = tid; s < HW; s += 1024) {
        float e = expf(a[s] - mx);
        p[s] = e;
        sum += e;
    }
    red[tid] = sum;
    __syncthreads();
    for (int st = 512; st > 0; st >>= 1) {
        if (tid < st) red[tid] += red[tid + st];
        __syncthreads();
    }
    float inv = 1.f / red[0];
    for (int s = tid; s < HW; s += 1024) p[s] *= inv;
}

// ---------------- m[h,c] = sum_s P[h,s]*K[c,s] ----------------
__global__ void k_m(const float* __restrict__ K) {
    int c = blockIdx.x * 8 + (threadIdx.x >> 5);
    int lane = threadIdx.x & 31;
    const float* kr = K + c * HW;
    float acc[NH] = {};
    for (int s = lane; s < HW; s += 32) {
        float kv = kr[s];
        #pragma unroll
        for (int h = 0; h < NH; h++) acc[h] += kv * g_P[h * HW + s];
    }
    #pragma unroll
    for (int h = 0; h < NH; h++) {
        #pragma unroll
        for (int o = 16; o > 0; o >>= 1) acc[h] += __shfl_down_sync(0xffffffffu, acc[h], o);
    }
    if (lane == 0) {
        #pragma unroll
        for (int h = 0; h < NH; h++) g_m[h * DK + c] = acc[h];
    }
}

__global__ void k_vproj(const float* __restrict__ Wv, const float* __restrict__ bv) {
    int r = blockIdx.x * 8 + (threadIdx.x >> 5);
    int lane = threadIdx.x & 31;
    int h = r >> 9;
    const float* mr = g_m + (h << 9);
    const float* wr = Wv + r * DK;
    float acc = 0.f;
    for (int c = lane; c < DK; c += 32) acc += wr[c] * mr[c];
    #pragma unroll
    for (int o = 16; o > 0; o >>= 1) acc += __shfl_down_sync(0xffffffffu, acc, o);
    if (lane == 0) g_x[r] = acc + bv[r];
}

__global__ void k_out(const float* __restrict__ Wo, const float* __restrict__ bo,
                      float* __restrict__ out) {
    int r = blockIdx.x * 8 + (threadIdx.x >> 5);
    int lane = threadIdx.x & 31;
    const float* wr = Wo + r * DHID;
    float acc = 0.f;
    for (int j = lane; j < DHID; j += 32) acc += wr[j] * g_x[j];
    #pragma unroll
    for (int o = 16; o > 0; o >>= 1) acc += __shfl_down_sync(0xffffffffu, acc, o);
    if (lane == 0) out[r] = acc + bo[r];
}

extern "C" void kernel_launch(void* const* d_in, const int* in_sizes, int n_in,
                              void* d_out, int out_size) {
    const float* Q    = (const float*)d_in[0];
    const float* K    = (const float*)d_in[1];
    const float* Wq   = (const float*)d_in[2];
    const float* bq   = (const float*)d_in[3];
    const float* Wk   = (const float*)d_in[4];
    const float* bk   = (const float*)d_in[5];
    const float* Wv   = (const float*)d_in[6];
    const float* bv   = (const float*)d_in[7];
    const float* Wo   = (const float*)d_in[8];
    const float* bo   = (const float*)d_in[9];
    const float* amp1 = (const float*)d_in[10];
    const float* amp2 = (const float*)d_in[11];
    const float* amp3 = (const float*)d_in[12];
    const float* pha1 = (const float*)d_in[13];
    const float* pha2 = (const float*)d_in[14];
    const float* pha3 = (const float*)d_in[15];
    const float* Wd1  = (const float*)d_in[16];
    const float* bd1  = (const float*)d_in[17];
    const float* Wd2  = (const float*)d_in[18];
    const float* bd2  = (const float*)d_in[19];
    float* out = (float*)d_out;

    // Fork a side stream for the attention-score chain (capturable fork-join).
    cudaStream_t s2;
    cudaEvent_t eFork, eJoin;
    cudaStreamCreateWithFlags(&s2, cudaStreamNonBlocking);
    cudaEventCreateWithFlags(&eFork, cudaEventDisableTiming);
    cudaEventCreateWithFlags(&eJoin, cudaEventDisableTiming);

    cudaEventRecord(eFork, 0);
    cudaStreamWaitEvent(s2, eFork, 0);

    // conv path on the main stream (positions k_mma<1> at launch #4 for ncu)
    k_tr1<<<1024, 256>>>(amp1, pha1);                                    // 1
    k_tr2<<<dim3(18, 16, 16), dim3(32, 8)>>>(amp2, pha2);                // 2
    k_mma<0><<<dim3(34, 8, 1), 256>>>(K);                                // 3
    k_mma<1><<<dim3(34, 4, 2), 256>>>(K);                                // 4
    k_f3p<<<dim3(9, 16, 2), 256>>>(amp3, pha3);
    k_f3red<<<dim3(133, 2), 256>>>();
    k_down<<<dim3(269, 2), 256>>>(Wd1, bd1, Wd2, bd2);

    // attention-score chain on the side stream (overlaps with conv path)
    k_qproj<<<512, 256, 0, s2>>>(Q, Wq, bq);
    k_qb<<<1, 256, 0, s2>>>(bk);
    k_u<<<dim3(8, 8), 512, 0, s2>>>(Wk);
    k_A0p<<<dim3(17, 8), 256, 0, s2>>>(K);
    k_fftrow<<<NH * HH, 64, 0, s2>>>();

    // join: fftcol_mod needs g_filt (main) and g_Fr (s2)
    cudaEventRecord(eJoin, s2);
    cudaStreamWaitEvent(0, eJoin, 0);

    k_fftcol_mod<<<68, 256>>>();
    k_invcol<<<68, 256>>>();
    k_invrow<<<133, 256>>>();
    k_softmax<<<NH, 1024>>>();

    // output path
    k_m<<<64, 256>>>(K);
    k_vproj<<<512, 256>>>(Wv, bv);
    k_out<<<64, 256>>>(Wo, bo, out);
}